// round 1
// baseline (speedup 1.0000x reference)
#include <cuda_runtime.h>
#include <math.h>

#define NB 1024
#define NS 100
#define NH 256
#define NL 20000
#define NU 20000
#define NEL 500000
#define NEU 400000

// ---------------- scratch layout (single __device__ global, no allocs) ------
#define OFF_ENCW 0ull                                    // [NL, NH] segment-sum result (loc graph)
#define OFF_EWU  (OFF_ENCW + (size_t)NL * NH)            // [NU, NH] segment-sum result (user graph)
#define OFF_XEMB (OFF_EWU  + (size_t)NU * NH)            // [NB*NS, NH] gathered x_emb
#define OFF_XP   (OFF_XEMB + (size_t)NB * NS * NH)       // [NB*NS, NH] x_emb @ W_ih^T + b_ih
#define OFF_SIM  (OFF_XP   + (size_t)NB * NS * NH)       // [NB, NS] user-loc similarity
#define OFF_WN   (OFF_SIM  + (size_t)NB * NS)            // [NB, NS] normalized weights w_j/denom
#define OFF_FEAT (OFF_WN   + (size_t)NB * NS)            // [NB, 3*NH] concat features
#define OFF_HA   (OFF_FEAT + (size_t)NB * 3 * NH)        // [NB, NH] RNN state ping
#define OFF_HB   (OFF_HA   + (size_t)NB * NH)            // [NB, NH] RNN state pong
#define OFF_NEED (OFF_HB   + (size_t)NB * NH)            // [NU] int flags (reused as float storage)
#define SCRATCH_FLOATS (OFF_NEED + (size_t)NU)

__device__ float g_scratch[SCRATCH_FLOATS];

// ---------------- small utility kernels -------------------------------------
__global__ void zero_k(float* __restrict__ p, int n) {
    int i = blockIdx.x * blockDim.x + threadIdx.x;
    if (i < n) p[i] = 0.0f;
}

__global__ void copy_k(float* __restrict__ dst, const float* __restrict__ src, int n) {
    int i = blockIdx.x * blockDim.x + threadIdx.x;
    if (i < n) dst[i] = src[i];
}

__global__ void mark_k(const int* __restrict__ uid, int* __restrict__ needed) {
    int i = blockIdx.x * blockDim.x + threadIdx.x;
    if (i < NB) needed[uid[i]] = 1;
}

// ---------------- segment-sum scatter: one block per edge -------------------
// out[row[e], :] += vals[e] * emb[col[e], :]
__global__ void scatter_loc_k(const int* __restrict__ row, const int* __restrict__ col,
                              const float* __restrict__ vals, const float* __restrict__ emb,
                              float* __restrict__ out) {
    int e = blockIdx.x;
    int c = threadIdx.x;                 // 256 threads = NH
    int r = row[e], cl = col[e];
    float v = vals[e];
    atomicAdd(out + (size_t)r * NH + c, v * emb[(size_t)cl * NH + c]);
}

// filtered version: skip edges whose destination user is not referenced
__global__ void scatter_usr_k(const int* __restrict__ row, const int* __restrict__ col,
                              const float* __restrict__ vals, const float* __restrict__ emb,
                              float* __restrict__ out, const int* __restrict__ needed) {
    int e = blockIdx.x;
    int r = row[e];
    if (!needed[r]) return;
    int c = threadIdx.x;
    int cl = col[e];
    float v = vals[e];
    atomicAdd(out + (size_t)r * NH + c, v * emb[(size_t)cl * NH + c]);
}

// ---------------- gather x_emb + user-loc similarity ------------------------
// one block per (b,s) pair, 256 threads (one per h)
__global__ void gather_sim_k(const int* __restrict__ fsm, const int* __restrict__ uid,
                             const float* __restrict__ encw, const float* __restrict__ ewu,
                             float* __restrict__ xemb, float* __restrict__ sim) {
    int pair = blockIdx.x;               // b*NS + s
    int h = threadIdx.x;
    int b = pair / NS;
    int loc = fsm[pair];
    float x = encw[(size_t)loc * NH + h];
    xemb[(size_t)pair * NH + h] = x;
    float u = ewu[(size_t)uid[b] * NH + h];
    float d = u - x;
    float ss = d * d;
    __shared__ float red[NH];
    red[h] = ss;
    __syncthreads();
    for (int o = NH / 2; o > 0; o >>= 1) {
        if (h < o) red[h] += red[h + o];
        __syncthreads();
    }
    if (h == 0) sim[pair] = expf(-sqrtf(red[0]));
}

// ---------------- decay weights + normalization -----------------------------
__global__ void weights_k(const float* __restrict__ td, const float* __restrict__ gd,
                          const float* __restrict__ sim, const int* __restrict__ length,
                          float* __restrict__ wn) {
    int b = blockIdx.x;
    int s = threadIdx.x;                 // 128 threads, S=100 valid
    __shared__ float red[128];
    float w = 0.0f;
    if (s < NS) {
        float t = td[b * NS + s];
        float a = (cosf(t * (6.2831853071795864769f / 86400.0f)) + 1.0f) * 0.5f
                  * expf(-t * (0.1f / 86400.0f));
        float bb = expf(-gd[b * NS + s] * 1000.0f);
        w = (a * bb + 1e-10f) * sim[b * NS + s];
        if (s >= length[b]) w = 0.0f;
    }
    red[s] = w;
    __syncthreads();
    for (int o = 64; o > 0; o >>= 1) {
        if (s < o) red[s] += red[s + o];
        __syncthreads();
    }
    float denom = red[0];
    if (s < NS) wn[b * NS + s] = w / denom;
}

// ---------------- generic TN SGEMM: C[M,N] = A[M,K] @ B[N,K]^T --------------
// EPI=0: C = acc + bias[n]
// EPI=1 (RNN step): v = tanh(acc + xp[(m*NS+s)*NH+n] + bias[n]);
//                   C[m*NH+n] = v; feat[m*3NH+n] += v * wn[m*NS+s]
template<int EPI>
__global__ __launch_bounds__(256)
void sgemm_tn(const float* __restrict__ A, const float* __restrict__ Bm,
              float* __restrict__ C, const float* __restrict__ bias,
              int M, int N, int K,
              const float* __restrict__ xp, const float* __restrict__ wn,
              float* __restrict__ feat, int s) {
    const int BM = 64, BN = 64, BK = 16;
    __shared__ __align__(16) float As[BK][BM];
    __shared__ __align__(16) float Bs[BK][BN];

    int tid = threadIdx.x;
    int m0 = blockIdx.y * BM, n0 = blockIdx.x * BN;
    int lr = tid >> 2;                 // 0..63 loader row
    int lc = (tid & 3) << 2;           // 0,4,8,12 loader k-offset
    int ty = tid >> 4;                 // 0..15
    int tx = tid & 15;                 // 0..15

    float acc[4][4];
#pragma unroll
    for (int i = 0; i < 4; i++)
#pragma unroll
        for (int j = 0; j < 4; j++) acc[i][j] = 0.0f;

    for (int k0 = 0; k0 < K; k0 += BK) {
        float4 av = *(const float4*)(A + (size_t)(m0 + lr) * K + k0 + lc);
        As[lc + 0][lr] = av.x; As[lc + 1][lr] = av.y;
        As[lc + 2][lr] = av.z; As[lc + 3][lr] = av.w;
        float4 bv = make_float4(0.f, 0.f, 0.f, 0.f);
        if (n0 + lr < N)
            bv = *(const float4*)(Bm + (size_t)(n0 + lr) * K + k0 + lc);
        Bs[lc + 0][lr] = bv.x; Bs[lc + 1][lr] = bv.y;
        Bs[lc + 2][lr] = bv.z; Bs[lc + 3][lr] = bv.w;
        __syncthreads();
#pragma unroll
        for (int kk = 0; kk < BK; kk++) {
            float4 a4 = *(const float4*)&As[kk][ty * 4];
            float4 b4 = *(const float4*)&Bs[kk][tx * 4];
            float ar[4] = {a4.x, a4.y, a4.z, a4.w};
            float br[4] = {b4.x, b4.y, b4.z, b4.w};
#pragma unroll
            for (int i = 0; i < 4; i++)
#pragma unroll
                for (int j = 0; j < 4; j++) acc[i][j] += ar[i] * br[j];
        }
        __syncthreads();
    }

#pragma unroll
    for (int i = 0; i < 4; i++) {
        int m = m0 + ty * 4 + i;
#pragma unroll
        for (int j = 0; j < 4; j++) {
            int n = n0 + tx * 4 + j;
            if (n < N) {
                float v = acc[i][j];
                if (EPI == 0) {
                    if (bias) v += bias[n];
                    C[(size_t)m * N + n] = v;
                } else {
                    v += xp[((size_t)m * NS + s) * NH + n] + bias[n];
                    v = tanhf(v);
                    C[(size_t)m * NH + n] = v;
                    feat[(size_t)m * 3 * NH + n] += v * wn[m * NS + s];
                }
            }
        }
    }
}

// ---------------- out_w2: weighted emb2 gather ------------------------------
__global__ void outw2_k(const int* __restrict__ fseq, const float* __restrict__ emb2,
                        const float* __restrict__ wn, float* __restrict__ feat) {
    int b = blockIdx.x;
    int h = threadIdx.x;                 // 256
    float acc = 0.0f;
    for (int s = 0; s < NS; s++) {
        int loc = fseq[b * NS + s];
        acc += emb2[(size_t)loc * NH + h] * wn[b * NS + s];
    }
    feat[(size_t)b * 3 * NH + 2 * NH + h] = acc;
}

// ---------------- p_u gather -------------------------------------------------
__global__ void pu_k(const int* __restrict__ uid, const float* __restrict__ user_emb,
                     float* __restrict__ feat) {
    int b = blockIdx.x;
    int h = threadIdx.x;
    feat[(size_t)b * 3 * NH + NH + h] = user_emb[(size_t)uid[b] * NH + h];
}

// ---------------- host launcher ----------------------------------------------
extern "C" void kernel_launch(void* const* d_in, const int* in_sizes, int n_in,
                              void* d_out, int out_size) {
    const int*   full_seq     = (const int*)d_in[0];
    const int*   full_seq_map = (const int*)d_in[1];
    const int*   length       = (const int*)d_in[2];
    const int*   user_id      = (const int*)d_in[3];
    const float* time_delta   = (const float*)d_in[4];
    const float* geo_delta    = (const float*)d_in[5];
    const float* enc_emb      = (const float*)d_in[6];
    const float* user_emb     = (const float*)d_in[7];
    const float* emb2         = (const float*)d_in[8];
    const int*   row_loc      = (const int*)d_in[9];
    const int*   col_loc      = (const int*)d_in[10];
    const float* vals_loc     = (const float*)d_in[11];
    const int*   row_usr      = (const int*)d_in[12];
    const int*   col_usr      = (const int*)d_in[13];
    const float* vals_usr     = (const float*)d_in[14];
    const float* W_ih         = (const float*)d_in[15];
    const float* W_hh         = (const float*)d_in[16];
    const float* b_ih         = (const float*)d_in[17];
    const float* b_hh         = (const float*)d_in[18];
    const float* W1           = (const float*)d_in[19];
    const float* b1           = (const float*)d_in[20];
    const float* h0           = (const float*)d_in[21];
    float* out = (float*)d_out;

    float* base = nullptr;
    cudaGetSymbolAddress((void**)&base, g_scratch);
    float* encw = base + OFF_ENCW;
    float* ewu  = base + OFF_EWU;
    float* xemb = base + OFF_XEMB;
    float* xp   = base + OFF_XP;
    float* sim  = base + OFF_SIM;
    float* wn   = base + OFF_WN;
    float* feat = base + OFF_FEAT;
    float* ha   = base + OFF_HA;
    float* hb   = base + OFF_HB;
    int*   needed = (int*)(base + OFF_NEED);

    // zero accumulators (encw+ewu are contiguous)
    {
        int n = (int)(2 * (size_t)NL * NH);
        zero_k<<<(n + 255) / 256, 256>>>(encw, n);
    }
    zero_k<<<(NB * 3 * NH + 255) / 256, 256>>>(feat, NB * 3 * NH);
    zero_k<<<(NU + 255) / 256, 256>>>((float*)needed, NU);
    mark_k<<<(NB + 255) / 256, 256>>>(user_id, needed);

    // segment sums (atomic scatter)
    scatter_loc_k<<<NEL, NH>>>(row_loc, col_loc, vals_loc, enc_emb, encw);
    scatter_usr_k<<<NEU, NH>>>(row_usr, col_usr, vals_usr, enc_emb, ewu, needed);

    // x_emb gather + similarity
    gather_sim_k<<<NB * NS, NH>>>(full_seq_map, user_id, encw, ewu, xemb, sim);

    // decay weights, masked + normalized
    weights_k<<<NB, 128>>>(time_delta, geo_delta, sim, length, wn);

    // XP = x_emb @ W_ih^T + b_ih  (M=102400, N=256, K=256)
    sgemm_tn<0><<<dim3(NH / 64, (NB * NS) / 64), 256>>>(
        xemb, W_ih, xp, b_ih, NB * NS, NH, NH, nullptr, nullptr, nullptr, 0);

    // RNN init + 100 fused steps (GEMM + tanh + weighted accumulation)
    copy_k<<<(NB * NH + 255) / 256, 256>>>(ha, h0, NB * NH);
    float* hc = ha;
    float* hn = hb;
    for (int s = 0; s < NS; s++) {
        sgemm_tn<1><<<dim3(NH / 64, NB / 64), 256>>>(
            hc, W_hh, hn, b_hh, NB, NH, NH, xp, wn, feat, s);
        float* t = hc; hc = hn; hn = t;
    }

    // out_w2 and p_u into feat
    outw2_k<<<NB, NH>>>(full_seq, emb2, wn, feat);
    pu_k<<<NB, NH>>>(user_id, user_emb, feat);

    // final: out = feat @ W1^T + b1  (M=1024, N=20000, K=768)
    sgemm_tn<0><<<dim3((NL + 63) / 64, NB / 64), 256>>>(
        feat, W1, out, b1, NB, NL, 3 * NH, nullptr, nullptr, nullptr, 0);
}